// round 8
// baseline (speedup 1.0000x reference)
#include <cuda_runtime.h>
#include <cstdint>
#include <math.h>

#define HW 4096
#define PW 68
#define PHW 4624          // 68*68, rows 16B-aligned
#define HIDC 128
#define BB 4
#define OO 8
#define CC 256

// 3-stage pipeline, K-chunk = 32: A 128*32*4 = 16384 B, B 32*136*4 = 17408 B
#define STAGE 33792
#define CONV_DSM (3*STAGE)   // 101376 B -> 2 CTA/SM

// ---------------------------------------------------------------------------
// Scratch (device globals; allocation forbidden). Zero-initialized at load;
// borders of padded buffers are NEVER written -> stay zero across replays.
// ---------------------------------------------------------------------------
__device__ float g_pst0[BB*OO*HIDC*PHW];     // padded states ping (tf32-rounded)
__device__ float g_pst1[BB*OO*HIDC*PHW];     // padded states pong
__device__ float g_pS[BB*HIDC*PHW];          // padded sum-over-objects (rounded)
__device__ float g_pfeats[BB*CC*PHW];        // padded feats (rounded)
__device__ float g_pbase[BB*HIDC*PHW];       // padded enc base (full fp32)
__device__ float g_T[BB*HIDC*HW];            // unpadded shared gcn term (fp32)
__device__ float g_rpart[4*BB*HW];           // readout base partials (4 cin slices)
__device__ float g_wencp[HIDC*CC*9];         // fragment-packed enc weights (tf32)
__device__ float g_w2p[HIDC*HIDC*9];         // fragment-packed W2
__device__ float g_wdp[HIDC*HIDC*9];         // fragment-packed W1-W2

// ---------------------------------------------------------------------------
__device__ __forceinline__ uint32_t f2tf32(float f) {
    uint32_t r; asm("cvt.rna.tf32.f32 %0, %1;" : "=r"(r) : "f"(f)); return r;
}
__device__ __forceinline__ float roundtf(float f) {
    return __uint_as_float(f2tf32(f));
}
#define CP16(dst, src) \
    asm volatile("cp.async.cg.shared.global [%0], [%1], 16;" \
                 :: "r"(dst), "l"(src) : "memory")

__device__ __forceinline__ void mma_tf32(float* c, const uint32_t* a,
                                         uint32_t b0, uint32_t b1) {
    asm("mma.sync.aligned.m16n8k8.row.col.f32.tf32.tf32.f32 "
        "{%0,%1,%2,%3}, {%4,%5,%6,%7}, {%8,%9}, {%0,%1,%2,%3};"
        : "+f"(c[0]), "+f"(c[1]), "+f"(c[2]), "+f"(c[3])
        : "r"(a[0]), "r"(a[1]), "r"(a[2]), "r"(a[3]), "r"(b0), "r"(b1));
}

// ---------------------------------------------------------------------------
// Implicit-GEMM 3x3 conv via mma.sync tf32, 3-stage cp.async pipeline (K=32
// chunks), single __syncthreads per chunk: at iter i the barrier guarantees
// compute(i-1) finished in all warps, so issue(i+2) may overwrite stage
// (i+2)%3 == (i-1)%3; wait_group(1) guarantees chunk i has landed.
// M=128 oc, N=128 px (2 image rows), K=9*CIN tap-major (32-k chunks, 1 tap).
// Block 256 thr (8 warps: 2 M x 4 N). grid (32 row-pairs, nImg). 2 CTA/SM.
// ---------------------------------------------------------------------------
template<int CIN>
__global__ void __launch_bounds__(256, 2)
conv_mma(const float* __restrict__ pin,
         const float* __restrict__ wpack,
         const float* __restrict__ bias,
         const float* __restrict__ addend, int addDiv,
         float* __restrict__ outp, int outPadded, int doRelu, int roundOut)
{
    extern __shared__ __align__(16) char dsm[];
    const int tid  = threadIdx.x;
    const int lane = tid & 31, wid = tid >> 5;
    const int wm   = wid & 1,  wn  = wid >> 1;
    const int img  = blockIdx.y, row0 = blockIdx.x * 2;
    constexpr int CPT = CIN / 32;         // chunks per tap
    constexpr int nchunk = CPT * 9;
    const float* pimg = pin + (long)img * CIN * PHW;
    const uint32_t smbase = (uint32_t)__cvta_generic_to_shared(dsm);

    float acc[4][4][4];
    #pragma unroll
    for (int mt = 0; mt < 4; mt++)
        #pragma unroll
        for (int nt = 0; nt < 4; nt++)
            #pragma unroll
            for (int e = 0; e < 4; e++) acc[mt][nt][e] = 0.f;

    auto issueChunk = [&](int i) {
        const int st = i % 3;
        const uint32_t abase = smbase + st * STAGE;
        const uint32_t bbase = abase + 16384;
        const float* asrc = wpack + (long)i * 4096;
        #pragma unroll
        for (int j = 0; j < 4; j++) {
            const int u = tid + j * 256;
            CP16(abase + u * 16, asrc + u * 4);
        }
        const int tap = i / CPT, cbase = (i - tap * CPT) * 32;
        const int y0 = row0 + (tap / 3 - 1) + 1;   // 0..65
        #pragma unroll
        for (int v = 0; v < 5; v++) {
            const int o = tid + v * 256;
            if (o < 1088) {
                const int cin = o / 34, rem = o - cin * 34;
                const int j = rem / 17, q = rem - j * 17;
                const float* src = pimg + (long)(cbase + cin) * PHW
                                   + (y0 + j) * PW + q * 4;
                const uint32_t dst = bbase + (cin * 136 + j * 68 + q * 4) * 4;
                CP16(dst, src);
            }
        }
        asm volatile("cp.async.commit_group;" ::: "memory");
    };

    auto compute = [&](int s, int dx) {
        const uint4*  As = (const uint4*)(dsm + s * STAGE);
        const float*  Bs = (const float*)(dsm + s * STAGE + 16384);
        #pragma unroll
        for (int kt = 0; kt < 4; kt++) {
            uint4 a[4];
            #pragma unroll
            for (int mt = 0; mt < 4; mt++)
                a[mt] = As[(kt * 8 + wm * 4 + mt) * 32 + lane];
            #pragma unroll
            for (int nt = 0; nt < 4; nt++) {
                const int n   = wn * 32 + nt * 8 + (lane >> 2);
                const int col = (n >> 6) * 68 + (n & 63) + 1 + dx;
                const float* bp = Bs + (kt * 8 + (lane & 3)) * 136 + col;
                const uint32_t b0 = __float_as_uint(bp[0]);
                const uint32_t b1 = __float_as_uint(bp[4 * 136]);
                #pragma unroll
                for (int mt = 0; mt < 4; mt++)
                    mma_tf32(acc[mt][nt], (const uint32_t*)&a[mt], b0, b1);
            }
        }
    };

    issueChunk(0); issueChunk(1);
    for (int i = 0; i < nchunk; i++) {
        asm volatile("cp.async.wait_group 1;" ::: "memory");
        __syncthreads();
        if (i + 2 < nchunk) issueChunk(i + 2);
        else asm volatile("cp.async.commit_group;" ::: "memory");
        compute(i % 3, (i / CPT) % 3 - 1);
    }

    // ---- epilogue
    const int addImg = addDiv ? (img / addDiv) : 0;
    #pragma unroll
    for (int mt = 0; mt < 4; mt++) {
        #pragma unroll
        for (int h = 0; h < 2; h++) {
            const int oc = wm * 64 + mt * 16 + (lane >> 2) + h * 8;
            const float bv = bias ? bias[oc] : 0.f;
            #pragma unroll
            for (int nt = 0; nt < 4; nt++) {
                const int n = wn * 32 + nt * 8 + 2 * (lane & 3);
                const int r = n >> 6, x = n & 63;
                float v0 = acc[mt][nt][2 * h + 0] + bv;
                float v1 = acc[mt][nt][2 * h + 1] + bv;
                if (addend) {
                    const float2 ad = *(const float2*)(addend
                        + ((long)addImg * HIDC + oc) * HW + (row0 + r) * 64 + x);
                    v0 += ad.x; v1 += ad.y;
                }
                if (doRelu) { v0 = fmaxf(v0, 0.f); v1 = fmaxf(v1, 0.f); }
                if (roundOut) { v0 = roundtf(v0); v1 = roundtf(v1); }
                if (outPadded) {
                    float* op = outp + ((long)img * HIDC + oc) * PHW
                                + (row0 + r + 1) * PW + 1 + x;
                    op[0] = v0; op[1] = v1;
                } else {
                    *(float2*)(outp + ((long)img * HIDC + oc) * HW
                               + (row0 + r) * 64 + x) = make_float2(v0, v1);
                }
            }
        }
    }
}

// ---------------------------------------------------------------------------
// Weight fragment packing, 32-k chunks (4096 floats each).
// Within chunk: kt(4) x mt(4) x lane(32) x e(4).
// a0:(r,c) a1:(r+8,c) a2:(r,c+4) a3:(r+8,c+4); r=lane>>2, c=lane&3.
// ---------------------------------------------------------------------------
__global__ void prep_enc_pack(const float* __restrict__ ew, float* __restrict__ wp) {
    int idx = blockIdx.x * 256 + threadIdx.x;
    if (idx >= HIDC * CC * 9) return;
    int i = idx >> 12, rem = idx & 4095;
    int kt = rem >> 10, r2 = rem & 1023;
    int mt = r2 >> 7, r3 = r2 & 127;
    int lane = r3 >> 2, e = r3 & 3;
    int oc = mt * 16 + (lane >> 2) + ((e & 1) << 3);
    int k  = i * 32 + kt * 8 + (lane & 3) + ((e >> 1) << 2);
    int tap = k / CC, cin = k % CC;
    wp[idx] = __uint_as_float(f2tf32(ew[((long)oc * 257 + cin) * 9 + tap]));
}
__global__ void prep_gcn_pack(const float* __restrict__ gw,
                              float* __restrict__ w2p, float* __restrict__ wdp) {
    int idx = blockIdx.x * 256 + threadIdx.x;
    if (idx >= HIDC * HIDC * 9) return;
    int i = idx >> 12, rem = idx & 4095;
    int kt = rem >> 10, r2 = rem & 1023;
    int mt = r2 >> 7, r3 = r2 & 127;
    int lane = r3 >> 2, e = r3 & 3;
    int oc = mt * 16 + (lane >> 2) + ((e & 1) << 3);
    int k  = i * 32 + kt * 8 + (lane & 3) + ((e >> 1) << 2);
    int tap = k / HIDC, cin = k % HIDC;
    float a = gw[((long)oc * 2 * HIDC + cin) * 9 + tap];
    float b = gw[((long)oc * 2 * HIDC + HIDC + cin) * 9 + tap];
    w2p[idx] = __uint_as_float(f2tf32(b));
    wdp[idx] = __uint_as_float(f2tf32(a - b));
}

// ---------------------------------------------------------------------------
// Pad / small kernels
// ---------------------------------------------------------------------------
__global__ void pad_feats_k(const float* __restrict__ f, float* __restrict__ pf) {
    long idx = (long)blockIdx.x * 256 + threadIdx.x;
    if (idx >= (long)BB * CC * PHW) return;
    long ch = idx / PHW; int p = (int)(idx % PHW); int y = p / PW, x = p % PW;
    float v = 0.f;
    if (y >= 1 && y <= 64 && x >= 1 && x <= 64)
        v = roundtf(f[ch * HW + (y - 1) * 64 + (x - 1)]);
    pf[idx] = v;
}
__global__ void sumO_k(const float* __restrict__ st, float* __restrict__ S) {
    long idx = (long)blockIdx.x * 256 + threadIdx.x;
    if (idx >= (long)BB * HIDC * PHW) return;
    int b = (int)(idx / (HIDC * PHW));
    long r = idx - (long)b * HIDC * PHW;
    const float* p = st + (long)b * OO * HIDC * PHW + r;
    float s = 0.f;
    #pragma unroll
    for (int o = 0; o < OO; o++) s += p[(long)o * HIDC * PHW];
    S[idx] = roundtf(s);
}
// enc per-object: states = round(relu(base + conv3x3(mask, enc_w[:,256])))
__global__ void __launch_bounds__(256) enc_obj_k(
    const float* __restrict__ masks, const float* __restrict__ enc_w,
    const float* __restrict__ pbase, float* __restrict__ pst)
{
    __shared__ float wm[HIDC * 9];
    const int tid = threadIdx.x;
    const int img = blockIdx.y;
    const int p   = blockIdx.x * 256 + tid;
    for (int t = tid; t < HIDC * 9; t += 256) {
        int oc = t / 9, k = t - oc * 9;
        wm[t] = enc_w[((long)oc * 257 + 256) * 9 + k];
    }
    __syncthreads();
    const int y = p >> 6, x = p & 63;
    float m[3][3];
    #pragma unroll
    for (int i = 0; i < 3; i++)
        #pragma unroll
        for (int j = 0; j < 3; j++) {
            int gy = y - 1 + i, gx = x - 1 + j;
            m[i][j] = ((unsigned)gy < 64u && (unsigned)gx < 64u)
                        ? masks[(long)img * HW + gy * 64 + gx] : 0.f;
        }
    const int b = img >> 3;
    const int pp = (y + 1) * PW + x + 1;
    const float* bimg = pbase + (long)b * HIDC * PHW;
    float* simg = pst + (long)img * HIDC * PHW;
    #pragma unroll 4
    for (int oc = 0; oc < HIDC; oc++) {
        float a = bimg[oc * PHW + pp];
        #pragma unroll
        for (int k = 0; k < 9; k++) a = fmaf(wm[oc * 9 + k], m[k / 3][k % 3], a);
        simg[oc * PHW + pp] = roundtf(fmaxf(a, 0.f));
    }
}
// readout base partials: rpart[slice][b] = (slice==0 ? ro_b : 0) +
//   conv3x3(feats[slice*64 .. +63], ro_w slice). grid (16, BB, 4)
__global__ void __launch_bounds__(256) ro_base_k(
    const float* __restrict__ feats, const float* __restrict__ ro_w,
    const float* __restrict__ ro_b, float* __restrict__ rpart)
{
    __shared__ float tile[18 * 18];
    __shared__ float ws[64 * 9];
    const int tid = threadIdx.x;
    const int img = blockIdx.y;
    const int sl  = blockIdx.z;
    const int tx0 = (blockIdx.x & 3) * 16, ty0 = (blockIdx.x >> 2) * 16;
    for (int t = tid; t < 64 * 9; t += 256) ws[t] = ro_w[sl * 64 * 9 + t];
    const int px = tid & 15, py = tid >> 4;
    float acc = (sl == 0) ? ro_b[0] : 0.f;
    const float* fimg = feats + ((long)img * CC + sl * 64) * HW;
    for (int ic = 0; ic < 64; ic++) {
        __syncthreads();
        for (int t = tid; t < 18 * 18; t += 256) {
            int yy = t / 18, xx = t - yy * 18;
            int gy = ty0 - 1 + yy, gx = tx0 - 1 + xx;
            tile[t] = ((unsigned)gy < 64u && (unsigned)gx < 64u)
                        ? fimg[(long)ic * HW + gy * 64 + gx] : 0.f;
        }
        __syncthreads();
        #pragma unroll
        for (int k = 0; k < 9; k++)
            acc = fmaf(ws[ic * 9 + k], tile[(py + k / 3) * 18 + px + (k % 3)], acc);
    }
    rpart[((long)sl * BB + img) * HW + (ty0 + py) * 64 + tx0 + px] = acc;
}
// readout per-object (padded, unrounded final states in)
__global__ void __launch_bounds__(256) ro_obj_k(
    const float* __restrict__ pst, const float* __restrict__ ro_w,
    const float* __restrict__ rpart, float* __restrict__ outp)
{
    __shared__ float tile[18 * 18];
    __shared__ float ws[HIDC * 9];
    const int tid = threadIdx.x;
    const int img = blockIdx.y;
    const int tx0 = (blockIdx.x & 3) * 16, ty0 = (blockIdx.x >> 2) * 16;
    for (int t = tid; t < HIDC * 9; t += 256) ws[t] = ro_w[(long)CC * 9 + t];
    const int px = tid & 15, py = tid >> 4;
    float acc = 0.f;
    const float* simg = pst + (long)img * HIDC * PHW;
    for (int ic = 0; ic < HIDC; ic++) {
        __syncthreads();
        for (int t = tid; t < 18 * 18; t += 256) {
            int yy = t / 18, xx = t - yy * 18;
            tile[t] = simg[(long)ic * PHW + (ty0 + yy) * PW + tx0 + xx];
        }
        __syncthreads();
        #pragma unroll
        for (int k = 0; k < 9; k++)
            acc = fmaf(ws[ic * 9 + k], tile[(py + k / 3) * 18 + px + (k % 3)], acc);
    }
    const int b = img >> 3;
    const long po = (long)b * HW + (ty0 + py) * 64 + tx0 + px;
    float z = acc + rpart[po] + rpart[(long)BB * HW + po]
              + rpart[2L * BB * HW + po] + rpart[3L * BB * HW + po];
    outp[(long)img * HW + (ty0 + py) * 64 + tx0 + px] = 1.f / (1.f + expf(-z));
}

// ---------------------------------------------------------------------------
extern "C" void kernel_launch(void* const* d_in, const int* in_sizes, int n_in,
                              void* d_out, int out_size)
{
    const float* feats = (const float*)d_in[0];
    const float* masks = (const float*)d_in[1];
    const float* enc_w = (const float*)d_in[4];
    const float* enc_b = (const float*)d_in[5];
    const float* gcn_w = (const float*)d_in[6];
    const float* gcn_b = (const float*)d_in[7];
    const float* ro_w  = (const float*)d_in[8];
    const float* ro_b  = (const float*)d_in[9];
    float* outp = (float*)d_out;

    float *pst0, *pst1, *pS, *pfeats, *pbase, *T, *rpart, *wencp, *w2p, *wdp;
    cudaGetSymbolAddress((void**)&pst0,   g_pst0);
    cudaGetSymbolAddress((void**)&pst1,   g_pst1);
    cudaGetSymbolAddress((void**)&pS,     g_pS);
    cudaGetSymbolAddress((void**)&pfeats, g_pfeats);
    cudaGetSymbolAddress((void**)&pbase,  g_pbase);
    cudaGetSymbolAddress((void**)&T,      g_T);
    cudaGetSymbolAddress((void**)&rpart,  g_rpart);
    cudaGetSymbolAddress((void**)&wencp,  g_wencp);
    cudaGetSymbolAddress((void**)&w2p,    g_w2p);
    cudaGetSymbolAddress((void**)&wdp,    g_wdp);

    cudaFuncSetAttribute(conv_mma<128>,
                         cudaFuncAttributeMaxDynamicSharedMemorySize, CONV_DSM);
    cudaFuncSetAttribute(conv_mma<256>,
                         cudaFuncAttributeMaxDynamicSharedMemorySize, CONV_DSM);

    prep_enc_pack<<<(HIDC*CC*9 + 255)/256, 256>>>(enc_w, wencp);
    prep_gcn_pack<<<(HIDC*HIDC*9 + 255)/256, 256>>>(gcn_w, w2p, wdp);
    pad_feats_k<<<(int)(((long)BB*CC*PHW + 255)/256), 256>>>(feats, pfeats);

    // enc base: conv(pfeats, enc_w[:, :256]) + enc_b -> padded base (fp32)
    conv_mma<256><<<dim3(32, BB), 256, CONV_DSM>>>(pfeats, wencp, enc_b,
                                                   nullptr, 0, pbase, 1, 0, 0);
    // enc per-object (stores rounded states)
    enc_obj_k<<<dim3(16, BB*OO), 256>>>(masks, enc_w, pbase, pst0);

    float* cur = pst0; float* nxt = pst1;
    for (int s = 0; s < 2; s++) {
        sumO_k<<<(int)(((long)BB*HIDC*PHW + 255)/256), 256>>>(cur, pS);
        // T = conv(S, W2) + gcn_b (unpadded fp32 out)
        conv_mma<128><<<dim3(32, BB), 256, CONV_DSM>>>(pS, w2p, gcn_b,
                                                       nullptr, 0, T, 0, 0, 0);
        // states' = relu(conv(states, Wd) + T); round unless final step
        conv_mma<128><<<dim3(32, BB*OO), 256, CONV_DSM>>>(cur, wdp, nullptr,
                                                          T, OO, nxt, 1, 1,
                                                          s == 0 ? 1 : 0);
        float* tmp = cur; cur = nxt; nxt = tmp;
    }

    ro_base_k<<<dim3(16, BB, 4), 256>>>(feats, ro_w, ro_b, rpart);
    ro_obj_k<<<dim3(16, BB*OO), 256>>>(cur, ro_w, rpart, outp);
}

// round 9
// speedup vs baseline: 1.6667x; 1.6667x over previous
#include <cuda_runtime.h>
#include <cuda_fp16.h>
#include <cstdint>
#include <math.h>

#define HW 4096
#define PW 72
#define PHW 5184          // 72*72 ; half2 rows 16B-aligned
#define HIDC 128
#define BB 4
#define OO 8
#define CC 256

// One chunk = 16 cin x 9 taps. A: 9kt*8mtile*32lane*16B = 36864 B.
// B: 8 ckpairs x (4 rows x 72 u32), ck stride 296 u32 (bank-spread) = 9472 B.
#define A_STAGE 36864
#define B_CKSTR 296
#define B_STAGE 9472
#define STAGE (A_STAGE + B_STAGE)      // 46336
#define CONV_DSM (2*STAGE)             // 92672 -> 2 CTA/SM

// ---------------------------------------------------------------------------
// Scratch (device globals; allocation forbidden). Zero-initialized at load;
// borders of padded buffers are NEVER written -> stay zero across replays.
// Padded activation buffers are half2, cin-pair interleaved: [ch/2][y][x].
// ---------------------------------------------------------------------------
__device__ uint32_t g_pst0[BB*OO*(HIDC/2)*PHW];  // states ping (half2)
__device__ uint32_t g_pst1[BB*OO*(HIDC/2)*PHW];  // states pong (half2)
__device__ uint32_t g_pS[BB*(HIDC/2)*PHW];       // sum-over-objects (half2)
__device__ uint32_t g_pfeats[BB*(CC/2)*PHW];     // feats (half2)
__device__ float    g_pbase[BB*HIDC*PHW];        // enc base (fp32 padded)
__device__ float    g_T[BB*HIDC*HW];             // shared gcn term (fp32)
__device__ float    g_stfin[BB*OO*HIDC*HW];      // final states (fp32 unpadded)
__device__ float    g_rpart[4*BB*HW];            // readout base partials
__device__ uint32_t g_wencp[HIDC*CC*9/2];        // packed fp16 enc weights
__device__ uint32_t g_w2p[HIDC*HIDC*9/2];        // packed W2
__device__ uint32_t g_wdp[HIDC*HIDC*9/2];        // packed W1-W2

// ---------------------------------------------------------------------------
#define CP16(dst, src) \
    asm volatile("cp.async.cg.shared.global [%0], [%1], 16;" \
                 :: "r"(dst), "l"(src) : "memory")

__device__ __forceinline__ uint32_t packh2(float lo, float hi) {
    __half2 h = __floats2half2_rn(lo, hi);
    return *(uint32_t*)&h;
}
__device__ __forceinline__ void mma_f16(float* c, const uint32_t* a,
                                        uint32_t b0, uint32_t b1) {
    asm("mma.sync.aligned.m16n8k16.row.col.f32.f16.f16.f32 "
        "{%0,%1,%2,%3}, {%4,%5,%6,%7}, {%8,%9}, {%0,%1,%2,%3};"
        : "+f"(c[0]), "+f"(c[1]), "+f"(c[2]), "+f"(c[3])
        : "r"(a[0]), "r"(a[1]), "r"(a[2]), "r"(a[3]), "r"(b0), "r"(b1));
}

// ---------------------------------------------------------------------------
// fp16 implicit-GEMM 3x3 conv. M=128 oc, N=128 px (2 rows), chunk = 16 cin x
// 9 taps (144 MMA/warp between barriers). 2-stage cp.async: at iter i the
// barrier proves compute(i-1) done, so issue(i+1) may overwrite stage (i+1)&1
// (computed at i-1); wait_group(0) proves chunk i landed. Copy overlaps
// compute. Block 256 (8 warps: 2M x 4N). grid (32 row-pairs, nImg). 2 CTA/SM.
// outMode: 0 = fp32 unpadded, 1 = half2 padded (oc-pair via shfl), 2 = fp32 padded.
// ---------------------------------------------------------------------------
template<int CIN>
__global__ void __launch_bounds__(256, 2)
conv_mma(const uint32_t* __restrict__ pin,
         const uint32_t* __restrict__ wpack,
         const float* __restrict__ bias,
         const float* __restrict__ addend, int addDiv,
         void* __restrict__ outp, int outMode, int doRelu)
{
    extern __shared__ __align__(16) char dsm[];
    const int tid  = threadIdx.x;
    const int lane = tid & 31, wid = tid >> 5;
    const int wm   = wid & 1,  wn  = wid >> 1;
    const int img  = blockIdx.y, row0 = blockIdx.x * 2;
    constexpr int nchunk = CIN / 16;
    const uint32_t* pimg = pin + (long)img * (CIN/2) * PHW;
    const uint32_t smbase = (uint32_t)__cvta_generic_to_shared(dsm);

    float acc[4][4][4];
    #pragma unroll
    for (int mt = 0; mt < 4; mt++)
        #pragma unroll
        for (int nt = 0; nt < 4; nt++)
            #pragma unroll
            for (int e = 0; e < 4; e++) acc[mt][nt][e] = 0.f;

    auto issueChunk = [&](int ci) {
        const uint32_t abase = smbase + (ci & 1) * STAGE;
        const uint32_t bbase = abase + A_STAGE;
        const uint32_t* asrc = wpack + (long)ci * 9216;
        #pragma unroll
        for (int j = 0; j < 9; j++) {                 // 2304 16B lines
            const int u = tid + j * 256;
            CP16(abase + u * 16, asrc + u * 4);
        }
        #pragma unroll
        for (int v = 0; v < 3; v++) {                 // 576 16B lines
            const int o = tid + v * 256;
            if (o < 576) {
                const int ck = o / 72, rem = o % 72;
                const int rI = rem / 18, q = rem % 18;
                const uint32_t* src = pimg + (long)(ci * 8 + ck) * PHW
                                      + (row0 + rI) * PW + q * 4;
                CP16(bbase + (ck * B_CKSTR + rI * 72 + q * 4) * 4, src);
            }
        }
        asm volatile("cp.async.commit_group;" ::: "memory");
    };

    auto compute = [&](int s) {
        const uint4*    As = (const uint4*)(dsm + s * STAGE);
        const uint32_t* Bs = (const uint32_t*)(dsm + s * STAGE + A_STAGE);
        #pragma unroll
        for (int kt = 0; kt < 9; kt++) {
            const int dy = kt / 3 - 1, dx = kt % 3 - 1;
            uint4 a[4];
            #pragma unroll
            for (int mt = 0; mt < 4; mt++)
                a[mt] = As[(kt * 8 + wm * 4 + mt) * 32 + lane];
            #pragma unroll
            for (int nt = 0; nt < 4; nt++) {
                const int n    = wn * 32 + nt * 8 + (lane >> 2);
                const int rowi = (n >> 6) + dy + 1;
                const int x    = (n & 63) + 1 + dx;
                const int c    = lane & 3;
                const uint32_t b0 = Bs[c * B_CKSTR + rowi * 72 + x];
                const uint32_t b1 = Bs[(c + 4) * B_CKSTR + rowi * 72 + x];
                #pragma unroll
                for (int mt = 0; mt < 4; mt++)
                    mma_f16(acc[mt][nt], (const uint32_t*)&a[mt], b0, b1);
            }
        }
    };

    issueChunk(0);
    for (int i = 0; i < nchunk; i++) {
        asm volatile("cp.async.wait_group 0;" ::: "memory");
        __syncthreads();
        if (i + 1 < nchunk) issueChunk(i + 1);
        compute(i & 1);
    }

    // ---- epilogue
    const int addImg = addDiv ? (img / addDiv) : 0;
    #pragma unroll
    for (int mt = 0; mt < 4; mt++) {
        #pragma unroll
        for (int h = 0; h < 2; h++) {
            const int oc = wm * 64 + mt * 16 + (lane >> 2) + h * 8;
            const float bv = bias ? bias[oc] : 0.f;
            #pragma unroll
            for (int nt = 0; nt < 4; nt++) {
                const int n = wn * 32 + nt * 8 + 2 * (lane & 3);
                const int r = n >> 6, x = n & 63;
                float v0 = acc[mt][nt][2 * h + 0] + bv;
                float v1 = acc[mt][nt][2 * h + 1] + bv;
                if (addend) {
                    const float2 ad = *(const float2*)(addend
                        + ((long)addImg * HIDC + oc) * HW + (row0 + r) * 64 + x);
                    v0 += ad.x; v1 += ad.y;
                }
                if (doRelu) { v0 = fmaxf(v0, 0.f); v1 = fmaxf(v1, 0.f); }
                if (outMode == 0) {
                    *(float2*)((float*)outp + ((long)img * HIDC + oc) * HW
                               + (row0 + r) * 64 + x) = make_float2(v0, v1);
                } else if (outMode == 2) {
                    float* op = (float*)outp + ((long)img * HIDC + oc) * PHW
                                + (row0 + r + 1) * PW + 1 + x;
                    op[0] = v0; op[1] = v1;
                } else {
                    const uint32_t own  = packh2(v0, v1);      // my oc, px x/x+1
                    const uint32_t part = __shfl_xor_sync(0xffffffffu, own, 4);
                    if (((lane >> 2) & 1) == 0) {              // even oc writes pair
                        uint32_t* op = (uint32_t*)outp
                            + ((long)img * (HIDC/2) + (oc >> 1)) * PHW
                            + (row0 + r + 1) * PW + 1 + x;
                        op[0] = (own & 0xFFFFu) | (part << 16);
                        op[1] = (own >> 16) | (part & 0xFFFF0000u);
                    }
                }
            }
        }
    }
}

// ---------------------------------------------------------------------------
// Weight packing (fp16 half2 of consecutive cin). u32 layout per chunk (9216):
// [kt(9)][mtile(8)][lane(32)][e(4)]; oc = mtile*16 + (lane>>2) + ((e&1)<<3);
// cinpair = (lane&3) + ((e>>1)<<2); cin0 = chunk*16 + cinpair*2; tap = kt.
// ---------------------------------------------------------------------------
__global__ void prep_enc_pack(const float* __restrict__ ew, uint32_t* __restrict__ wp) {
    int idx = blockIdx.x * 256 + threadIdx.x;
    if (idx >= HIDC * CC * 9 / 2) return;
    int chunk = idx / 9216, rem = idx % 9216;
    int kt = rem / 1024, rem2 = rem % 1024;
    int mtile = rem2 / 128, r3 = rem2 % 128;
    int lane = r3 / 4, e = r3 % 4;
    int oc = mtile * 16 + (lane >> 2) + ((e & 1) << 3);
    int cin0 = chunk * 16 + ((lane & 3) + ((e >> 1) << 2)) * 2;
    float w0 = ew[((long)oc * 257 + cin0) * 9 + kt];
    float w1 = ew[((long)oc * 257 + cin0 + 1) * 9 + kt];
    wp[idx] = packh2(w0, w1);
}
__global__ void prep_gcn_pack(const float* __restrict__ gw,
                              uint32_t* __restrict__ w2p, uint32_t* __restrict__ wdp) {
    int idx = blockIdx.x * 256 + threadIdx.x;
    if (idx >= HIDC * HIDC * 9 / 2) return;
    int chunk = idx / 9216, rem = idx % 9216;
    int kt = rem / 1024, rem2 = rem % 1024;
    int mtile = rem2 / 128, r3 = rem2 % 128;
    int lane = r3 / 4, e = r3 % 4;
    int oc = mtile * 16 + (lane >> 2) + ((e & 1) << 3);
    int cin0 = chunk * 16 + ((lane & 3) + ((e >> 1) << 2)) * 2;
    float a0 = gw[((long)oc * 2 * HIDC + cin0) * 9 + kt];
    float b0 = gw[((long)oc * 2 * HIDC + HIDC + cin0) * 9 + kt];
    float a1 = gw[((long)oc * 2 * HIDC + cin0 + 1) * 9 + kt];
    float b1 = gw[((long)oc * 2 * HIDC + HIDC + cin0 + 1) * 9 + kt];
    w2p[idx] = packh2(b0, b1);
    wdp[idx] = packh2(a0 - b0, a1 - b1);
}

// ---------------------------------------------------------------------------
// Pad / small kernels
// ---------------------------------------------------------------------------
__global__ void pad_feats_k(const float* __restrict__ f, uint32_t* __restrict__ pf) {
    long idx = (long)blockIdx.x * 256 + threadIdx.x;
    if (idx >= (long)BB * (CC/2) * PHW) return;
    long ch = idx / PHW; int p = (int)(idx % PHW); int y = p / PW, x = p % PW;
    uint32_t v = 0;
    if (y >= 1 && y <= 64 && x >= 1 && x <= 64) {
        int b = (int)(ch >> 7), ck = (int)(ch & 127);
        const float* src = f + ((long)b * CC + 2 * ck) * HW + (y - 1) * 64 + (x - 1);
        v = packh2(src[0], src[HW]);
    }
    pf[idx] = v;
}
__global__ void sumO_k(const uint32_t* __restrict__ st, uint32_t* __restrict__ S) {
    long idx = (long)blockIdx.x * 256 + threadIdx.x;
    if (idx >= (long)BB * (HIDC/2) * PHW) return;
    int b = (int)(idx / ((HIDC/2) * PHW));
    long r = idx - (long)b * (HIDC/2) * PHW;
    const uint32_t* p = st + (long)b * OO * (HIDC/2) * PHW + r;
    float lo = 0.f, hi = 0.f;
    #pragma unroll
    for (int o = 0; o < OO; o++) {
        __half2 h = *(const __half2*)&p[(long)o * (HIDC/2) * PHW];
        lo += __low2float(h); hi += __high2float(h);
    }
    S[idx] = packh2(lo, hi);
}
// enc per-object: states = half2(relu(base + conv3x3(mask, enc_w[:,256])))
__global__ void __launch_bounds__(256) enc_obj_k(
    const float* __restrict__ masks, const float* __restrict__ enc_w,
    const float* __restrict__ pbase, uint32_t* __restrict__ pst)
{
    __shared__ float wm[HIDC * 9];
    const int tid = threadIdx.x;
    const int img = blockIdx.y;
    const int p   = blockIdx.x * 256 + tid;
    for (int t = tid; t < HIDC * 9; t += 256) {
        int oc = t / 9, k = t - oc * 9;
        wm[t] = enc_w[((long)oc * 257 + 256) * 9 + k];
    }
    __syncthreads();
    const int y = p >> 6, x = p & 63;
    float m[3][3];
    #pragma unroll
    for (int i = 0; i < 3; i++)
        #pragma unroll
        for (int j = 0; j < 3; j++) {
            int gy = y - 1 + i, gx = x - 1 + j;
            m[i][j] = ((unsigned)gy < 64u && (unsigned)gx < 64u)
                        ? masks[(long)img * HW + gy * 64 + gx] : 0.f;
        }
    const int b = img >> 3;
    const int pp = (y + 1) * PW + x + 1;
    const float* bimg = pbase + (long)b * HIDC * PHW;
    uint32_t* simg = pst + (long)img * (HIDC/2) * PHW;
    #pragma unroll 2
    for (int j = 0; j < HIDC/2; j++) {
        float a0 = bimg[(2*j) * PHW + pp];
        float a1 = bimg[(2*j+1) * PHW + pp];
        #pragma unroll
        for (int k = 0; k < 9; k++) {
            a0 = fmaf(wm[(2*j) * 9 + k],   m[k/3][k%3], a0);
            a1 = fmaf(wm[(2*j+1) * 9 + k], m[k/3][k%3], a1);
        }
        simg[j * PHW + pp] = packh2(fmaxf(a0, 0.f), fmaxf(a1, 0.f));
    }
}
// readout base partials (4 cin slices, fp32 feats). grid (16, BB, 4)
__global__ void __launch_bounds__(256) ro_base_k(
    const float* __restrict__ feats, const float* __restrict__ ro_w,
    const float* __restrict__ ro_b, float* __restrict__ rpart)
{
    __shared__ float tile[18 * 18];
    __shared__ float ws[64 * 9];
    const int tid = threadIdx.x;
    const int img = blockIdx.y;
    const int sl  = blockIdx.z;
    const int tx0 = (blockIdx.x & 3) * 16, ty0 = (blockIdx.x >> 2) * 16;
    for (int t = tid; t < 64 * 9; t += 256) ws[t] = ro_w[sl * 64 * 9 + t];
    const int px = tid & 15, py = tid >> 4;
    float acc = (sl == 0) ? ro_b[0] : 0.f;
    const float* fimg = feats + ((long)img * CC + sl * 64) * HW;
    for (int ic = 0; ic < 64; ic++) {
        __syncthreads();
        for (int t = tid; t < 18 * 18; t += 256) {
            int yy = t / 18, xx = t - yy * 18;
            int gy = ty0 - 1 + yy, gx = tx0 - 1 + xx;
            tile[t] = ((unsigned)gy < 64u && (unsigned)gx < 64u)
                        ? fimg[(long)ic * HW + gy * 64 + gx] : 0.f;
        }
        __syncthreads();
        #pragma unroll
        for (int k = 0; k < 9; k++)
            acc = fmaf(ws[ic * 9 + k], tile[(py + k / 3) * 18 + px + (k % 3)], acc);
    }
    rpart[((long)sl * BB + img) * HW + (ty0 + py) * 64 + tx0 + px] = acc;
}
// readout per-object: final states fp32 UNPADDED in
__global__ void __launch_bounds__(256) ro_obj_k(
    const float* __restrict__ stfin, const float* __restrict__ ro_w,
    const float* __restrict__ rpart, float* __restrict__ outp)
{
    __shared__ float tile[18 * 18];
    __shared__ float ws[HIDC * 9];
    const int tid = threadIdx.x;
    const int img = blockIdx.y;
    const int tx0 = (blockIdx.x & 3) * 16, ty0 = (blockIdx.x >> 2) * 16;
    for (int t = tid; t < HIDC * 9; t += 256) ws[t] = ro_w[(long)CC * 9 + t];
    const int px = tid & 15, py = tid >> 4;
    float acc = 0.f;
    const float* simg = stfin + (long)img * HIDC * HW;
    for (int ic = 0; ic < HIDC; ic++) {
        __syncthreads();
        for (int t = tid; t < 18 * 18; t += 256) {
            int yy = t / 18, xx = t - yy * 18;
            int gy = ty0 - 1 + yy, gx = tx0 - 1 + xx;
            tile[t] = ((unsigned)gy < 64u && (unsigned)gx < 64u)
                        ? simg[(long)ic * HW + gy * 64 + gx] : 0.f;
        }
        __syncthreads();
        #pragma unroll
        for (int k = 0; k < 9; k++)
            acc = fmaf(ws[ic * 9 + k], tile[(py + k / 3) * 18 + px + (k % 3)], acc);
    }
    const int b = img >> 3;
    const long po = (long)b * HW + (ty0 + py) * 64 + tx0 + px;
    float z = acc + rpart[po] + rpart[(long)BB * HW + po]
              + rpart[2L * BB * HW + po] + rpart[3L * BB * HW + po];
    outp[(long)img * HW + (ty0 + py) * 64 + tx0 + px] = 1.f / (1.f + expf(-z));
}

// ---------------------------------------------------------------------------
extern "C" void kernel_launch(void* const* d_in, const int* in_sizes, int n_in,
                              void* d_out, int out_size)
{
    const float* feats = (const float*)d_in[0];
    const float* masks = (const float*)d_in[1];
    const float* enc_w = (const float*)d_in[4];
    const float* enc_b = (const float*)d_in[5];
    const float* gcn_w = (const float*)d_in[6];
    const float* gcn_b = (const float*)d_in[7];
    const float* ro_w  = (const float*)d_in[8];
    const float* ro_b  = (const float*)d_in[9];
    float* outp = (float*)d_out;

    uint32_t *pst0, *pst1, *pS, *pfeats, *wencp, *w2p, *wdp;
    float *pbase, *T, *stfin, *rpart;
    cudaGetSymbolAddress((void**)&pst0,   g_pst0);
    cudaGetSymbolAddress((void**)&pst1,   g_pst1);
    cudaGetSymbolAddress((void**)&pS,     g_pS);
    cudaGetSymbolAddress((void**)&pfeats, g_pfeats);
    cudaGetSymbolAddress((void**)&pbase,  g_pbase);
    cudaGetSymbolAddress((void**)&T,      g_T);
    cudaGetSymbolAddress((void**)&stfin,  g_stfin);
    cudaGetSymbolAddress((void**)&rpart,  g_rpart);
    cudaGetSymbolAddress((void**)&wencp,  g_wencp);
    cudaGetSymbolAddress((void**)&w2p,    g_w2p);
    cudaGetSymbolAddress((void**)&wdp,    g_wdp);

    cudaFuncSetAttribute(conv_mma<128>,
                         cudaFuncAttributeMaxDynamicSharedMemorySize, CONV_DSM);
    cudaFuncSetAttribute(conv_mma<256>,
                         cudaFuncAttributeMaxDynamicSharedMemorySize, CONV_DSM);

    prep_enc_pack<<<(HIDC*CC*9/2 + 255)/256, 256>>>(enc_w, wencp);
    prep_gcn_pack<<<(HIDC*HIDC*9/2 + 255)/256, 256>>>(gcn_w, w2p, wdp);
    pad_feats_k<<<(int)(((long)BB*(CC/2)*PHW + 255)/256), 256>>>(feats, pfeats);

    // enc base: conv(pfeats, enc_w[:, :256]) + enc_b -> fp32 padded base
    conv_mma<256><<<dim3(32, BB), 256, CONV_DSM>>>(pfeats, wencp, enc_b,
                                                   nullptr, 0, pbase, 2, 0);
    // enc per-object -> half2 states
    enc_obj_k<<<dim3(16, BB*OO), 256>>>(masks, enc_w, pbase, pst0);

    uint32_t* cur = pst0; uint32_t* nxt = pst1;
    for (int s = 0; s < 2; s++) {
        sumO_k<<<(int)(((long)BB*(HIDC/2)*PHW + 255)/256), 256>>>(cur, pS);
        // T = conv(S, W2) + gcn_b (fp32 unpadded)
        conv_mma<128><<<dim3(32, BB), 256, CONV_DSM>>>(pS, w2p, gcn_b,
                                                       nullptr, 0, T, 0, 0);
        // states' = relu(conv(states, Wd) + T)
        if (s == 0) {
            conv_mma<128><<<dim3(32, BB*OO), 256, CONV_DSM>>>(cur, wdp, nullptr,
                                                              T, OO, nxt, 1, 1);
            uint32_t* tmp = cur; cur = nxt; nxt = tmp;
        } else {
            conv_mma<128><<<dim3(32, BB*OO), 256, CONV_DSM>>>(cur, wdp, nullptr,
                                                              T, OO, stfin, 0, 1);
        }
    }

    ro_base_k<<<dim3(16, BB, 4), 256>>>(feats, ro_w, ro_b, rpart);
    ro_obj_k<<<dim3(16, BB*OO), 256>>>(stfin, ro_w, rpart, outp);
}

// round 10
// speedup vs baseline: 2.4165x; 1.4499x over previous
#include <cuda_runtime.h>
#include <cuda_fp16.h>
#include <cstdint>
#include <math.h>

#define HW 4096
#define PW 72
#define PHW 5184          // 72*72 ; half2 rows 16B-aligned
#define HIDC 128
#define BB 4
#define OO 8
#define CC 256

// One chunk = 16 cin x 9 taps. A: 9kt*8mtile*32lane*16B = 36864 B.
// B: 8 ckpairs x (4 rows x 72 u32), ck stride 296 u32 (bank-spread) = 9472 B.
#define A_STAGE 36864
#define B_CKSTR 296
#define B_STAGE 9472
#define STAGE (A_STAGE + B_STAGE)      // 46336
#define CONV_DSM (2*STAGE)             // 92672 -> 2 CTA/SM

// Readout tile kernels: 64 ck x 4 rows staged once. 64*296 u32 tile.
#define RO_TILE_U32 18944
#define RO_DSM ((RO_TILE_U32 + 576)*4 + 1024)   // tile + ws + reduce buf

// ---------------------------------------------------------------------------
// Scratch (device globals; allocation forbidden). Zero-initialized at load;
// borders of padded buffers are NEVER written -> stay zero across replays.
// Padded activation buffers are half2, cin-pair interleaved: [ch/2][y][x].
// ---------------------------------------------------------------------------
__device__ uint32_t g_pst0[BB*OO*(HIDC/2)*PHW];  // states ping (half2)
__device__ uint32_t g_pst1[BB*OO*(HIDC/2)*PHW];  // states pong (half2)
__device__ uint32_t g_pS[BB*(HIDC/2)*PHW];       // sum-over-objects (half2)
__device__ uint32_t g_pfeats[BB*(CC/2)*PHW];     // feats (half2)
__device__ float    g_pbase[2*BB*HIDC*PHW];      // enc base partials (fp32 padded)
__device__ float    g_T[2*BB*HIDC*HW];           // gcn term partials (fp32)
__device__ float    g_rpart[2*BB*HW];            // readout base partials
__device__ uint32_t g_wencp[HIDC*CC*9/2];        // packed fp16 enc weights
__device__ uint32_t g_w2p[HIDC*HIDC*9/2];        // packed W2
__device__ uint32_t g_wdp[HIDC*HIDC*9/2];        // packed W1-W2
__device__ uint32_t g_wrof[2*9*64];              // packed ro feats weights
__device__ uint32_t g_wroh[9*64];                // packed ro hid weights

// ---------------------------------------------------------------------------
#define CP16(dst, src) \
    asm volatile("cp.async.cg.shared.global [%0], [%1], 16;" \
                 :: "r"(dst), "l"(src) : "memory")

__device__ __forceinline__ uint32_t packh2(float lo, float hi) {
    __half2 h = __floats2half2_rn(lo, hi);
    return *(uint32_t*)&h;
}
__device__ __forceinline__ void mma_f16(float* c, const uint32_t* a,
                                        uint32_t b0, uint32_t b1) {
    asm("mma.sync.aligned.m16n8k16.row.col.f32.f16.f16.f32 "
        "{%0,%1,%2,%3}, {%4,%5,%6,%7}, {%8,%9}, {%0,%1,%2,%3};"
        : "+f"(c[0]), "+f"(c[1]), "+f"(c[2]), "+f"(c[3])
        : "r"(a[0]), "r"(a[1]), "r"(a[2]), "r"(a[3]), "r"(b0), "r"(b1));
}

// ---------------------------------------------------------------------------
// fp16 implicit-GEMM 3x3 conv. M=128 oc, N=128 px (2 rows), chunk = 16 cin x
// 9 taps. 2-stage cp.async, single barrier per chunk. Optional K-split via
// blockIdx.z (each z-half writes its own output buffer; bias only on z==0).
// outMode: 0 = fp32 unpadded, 1 = half2 padded (oc-pair via shfl), 2 = fp32 padded.
// ---------------------------------------------------------------------------
template<int CIN>
__global__ void __launch_bounds__(256, 2)
conv_mma(const uint32_t* __restrict__ pin, long imgCkStride,
         const uint32_t* __restrict__ wpack,
         const float* __restrict__ bias,
         const float* __restrict__ addend, const float* __restrict__ addend2,
         int addDiv,
         void* __restrict__ outp, long outZStride, int outMode, int doRelu)
{
    extern __shared__ __align__(16) char dsm[];
    const int tid  = threadIdx.x;
    const int lane = tid & 31, wid = tid >> 5;
    const int wm   = wid & 1,  wn  = wid >> 1;
    const int img  = blockIdx.y, row0 = blockIdx.x * 2, z = blockIdx.z;
    constexpr int nchunk = CIN / 16;
    const uint32_t* pimg = pin + (long)img * imgCkStride + (long)z * (CIN/2) * PHW;
    const uint32_t* wp   = wpack + (long)z * (CIN/16) * 9216;
    const uint32_t smbase = (uint32_t)__cvta_generic_to_shared(dsm);

    float acc[4][4][4];
    #pragma unroll
    for (int mt = 0; mt < 4; mt++)
        #pragma unroll
        for (int nt = 0; nt < 4; nt++)
            #pragma unroll
            for (int e = 0; e < 4; e++) acc[mt][nt][e] = 0.f;

    auto issueChunk = [&](int ci) {
        const uint32_t abase = smbase + (ci & 1) * STAGE;
        const uint32_t bbase = abase + A_STAGE;
        const uint32_t* asrc = wp + (long)ci * 9216;
        #pragma unroll
        for (int j = 0; j < 9; j++) {                 // 2304 16B lines
            const int u = tid + j * 256;
            CP16(abase + u * 16, asrc + u * 4);
        }
        #pragma unroll
        for (int v = 0; v < 3; v++) {                 // 576 16B lines
            const int o = tid + v * 256;
            if (o < 576) {
                const int ck = o / 72, rem = o % 72;
                const int rI = rem / 18, q = rem % 18;
                const uint32_t* src = pimg + (long)(ci * 8 + ck) * PHW
                                      + (row0 + rI) * PW + q * 4;
                CP16(bbase + (ck * B_CKSTR + rI * 72 + q * 4) * 4, src);
            }
        }
        asm volatile("cp.async.commit_group;" ::: "memory");
    };

    auto compute = [&](int s) {
        const uint4*    As = (const uint4*)(dsm + s * STAGE);
        const uint32_t* Bs = (const uint32_t*)(dsm + s * STAGE + A_STAGE);
        #pragma unroll
        for (int kt = 0; kt < 9; kt++) {
            const int dy = kt / 3 - 1, dx = kt % 3 - 1;
            uint4 a[4];
            #pragma unroll
            for (int mt = 0; mt < 4; mt++)
                a[mt] = As[(kt * 8 + wm * 4 + mt) * 32 + lane];
            #pragma unroll
            for (int nt = 0; nt < 4; nt++) {
                const int n    = wn * 32 + nt * 8 + (lane >> 2);
                const int rowi = (n >> 6) + dy + 1;
                const int x    = (n & 63) + 1 + dx;
                const int c    = lane & 3;
                const uint32_t b0 = Bs[c * B_CKSTR + rowi * 72 + x];
                const uint32_t b1 = Bs[(c + 4) * B_CKSTR + rowi * 72 + x];
                #pragma unroll
                for (int mt = 0; mt < 4; mt++)
                    mma_f16(acc[mt][nt], (const uint32_t*)&a[mt], b0, b1);
            }
        }
    };

    issueChunk(0);
    for (int i = 0; i < nchunk; i++) {
        asm volatile("cp.async.wait_group 0;" ::: "memory");
        __syncthreads();
        if (i + 1 < nchunk) issueChunk(i + 1);
        compute(i & 1);
    }

    // ---- epilogue
    const int addImg = addDiv ? (img / addDiv) : 0;
    #pragma unroll
    for (int mt = 0; mt < 4; mt++) {
        #pragma unroll
        for (int h = 0; h < 2; h++) {
            const int oc = wm * 64 + mt * 16 + (lane >> 2) + h * 8;
            const float bv = (bias && z == 0) ? bias[oc] : 0.f;
            #pragma unroll
            for (int nt = 0; nt < 4; nt++) {
                const int n = wn * 32 + nt * 8 + 2 * (lane & 3);
                const int r = n >> 6, x = n & 63;
                float v0 = acc[mt][nt][2 * h + 0] + bv;
                float v1 = acc[mt][nt][2 * h + 1] + bv;
                const long aoff = ((long)addImg * HIDC + oc) * HW + (row0 + r) * 64 + x;
                if (addend) {
                    const float2 ad = *(const float2*)(addend + aoff);
                    v0 += ad.x; v1 += ad.y;
                }
                if (addend2) {
                    const float2 ad = *(const float2*)(addend2 + aoff);
                    v0 += ad.x; v1 += ad.y;
                }
                if (doRelu) { v0 = fmaxf(v0, 0.f); v1 = fmaxf(v1, 0.f); }
                if (outMode == 0) {
                    *(float2*)((float*)outp + z * outZStride
                               + ((long)img * HIDC + oc) * HW
                               + (row0 + r) * 64 + x) = make_float2(v0, v1);
                } else if (outMode == 2) {
                    float* op = (float*)outp + z * outZStride
                                + ((long)img * HIDC + oc) * PHW
                                + (row0 + r + 1) * PW + 1 + x;
                    op[0] = v0; op[1] = v1;
                } else {
                    const uint32_t own  = packh2(v0, v1);      // my oc, px x/x+1
                    const uint32_t part = __shfl_xor_sync(0xffffffffu, own, 4);
                    if (((lane >> 2) & 1) == 0) {              // even oc writes pair
                        uint32_t* op = (uint32_t*)outp
                            + ((long)img * (HIDC/2) + (oc >> 1)) * PHW
                            + (row0 + r + 1) * PW + 1 + x;
                        op[0] = (own & 0xFFFFu) | (part << 16);
                        op[1] = (own >> 16) | (part & 0xFFFF0000u);
                    }
                }
            }
        }
    }
}

// ---------------------------------------------------------------------------
// Weight packing (fp16 half2 of consecutive cin). u32 layout per chunk (9216):
// [kt(9)][mtile(8)][lane(32)][e(4)]; oc = mtile*16 + (lane>>2) + ((e&1)<<3);
// cinpair = (lane&3) + ((e>>1)<<2); cin0 = chunk*16 + cinpair*2; tap = kt.
// ---------------------------------------------------------------------------
__global__ void prep_enc_pack(const float* __restrict__ ew, uint32_t* __restrict__ wp) {
    int idx = blockIdx.x * 256 + threadIdx.x;
    if (idx >= HIDC * CC * 9 / 2) return;
    int chunk = idx / 9216, rem = idx % 9216;
    int kt = rem / 1024, rem2 = rem % 1024;
    int mtile = rem2 / 128, r3 = rem2 % 128;
    int lane = r3 / 4, e = r3 % 4;
    int oc = mtile * 16 + (lane >> 2) + ((e & 1) << 3);
    int cin0 = chunk * 16 + ((lane & 3) + ((e >> 1) << 2)) * 2;
    float w0 = ew[((long)oc * 257 + cin0) * 9 + kt];
    float w1 = ew[((long)oc * 257 + cin0 + 1) * 9 + kt];
    wp[idx] = packh2(w0, w1);
}
__global__ void prep_gcn_pack(const float* __restrict__ gw,
                              uint32_t* __restrict__ w2p, uint32_t* __restrict__ wdp) {
    int idx = blockIdx.x * 256 + threadIdx.x;
    if (idx >= HIDC * HIDC * 9 / 2) return;
    int chunk = idx / 9216, rem = idx % 9216;
    int kt = rem / 1024, rem2 = rem % 1024;
    int mtile = rem2 / 128, r3 = rem2 % 128;
    int lane = r3 / 4, e = r3 % 4;
    int oc = mtile * 16 + (lane >> 2) + ((e & 1) << 3);
    int cin0 = chunk * 16 + ((lane & 3) + ((e >> 1) << 2)) * 2;
    float a0 = gw[((long)oc * 2 * HIDC + cin0) * 9 + kt];
    float b0 = gw[((long)oc * 2 * HIDC + HIDC + cin0) * 9 + kt];
    float a1 = gw[((long)oc * 2 * HIDC + cin0 + 1) * 9 + kt];
    float b1 = gw[((long)oc * 2 * HIDC + HIDC + cin0 + 1) * 9 + kt];
    w2p[idx] = packh2(b0, b1);
    wdp[idx] = packh2(a0 - b0, a1 - b1);
}
// ro weights: wrof[z(2)][tap(9)][ck(64)] (feats ch z*128+2ck), wroh[tap][ck]
__global__ void prep_ro_pack(const float* __restrict__ ro_w,
                             uint32_t* __restrict__ wrof, uint32_t* __restrict__ wroh) {
    int idx = blockIdx.x * 256 + threadIdx.x;
    if (idx < 1152) {
        int zz = idx / 576, r = idx % 576, tap = r / 64, ck = r % 64;
        int ch0 = zz * 128 + 2 * ck;
        wrof[idx] = packh2(ro_w[ch0 * 9 + tap], ro_w[(ch0 + 1) * 9 + tap]);
    } else if (idx < 1152 + 576) {
        int r = idx - 1152, tap = r / 64, ck = r % 64;
        int ch0 = CC + 2 * ck;
        wroh[r] = packh2(ro_w[ch0 * 9 + tap], ro_w[(ch0 + 1) * 9 + tap]);
    }
}

// ---------------------------------------------------------------------------
// Pad / small kernels
// ---------------------------------------------------------------------------
__global__ void pad_feats_k(const float* __restrict__ f, uint32_t* __restrict__ pf) {
    long idx = (long)blockIdx.x * 256 + threadIdx.x;
    if (idx >= (long)BB * (CC/2) * PHW) return;
    long ch = idx / PHW; int p = (int)(idx % PHW); int y = p / PW, x = p % PW;
    uint32_t v = 0;
    if (y >= 1 && y <= 64 && x >= 1 && x <= 64) {
        int b = (int)(ch >> 7), ck = (int)(ch & 127);
        const float* src = f + ((long)b * CC + 2 * ck) * HW + (y - 1) * 64 + (x - 1);
        v = packh2(src[0], src[HW]);
    }
    pf[idx] = v;
}
__global__ void sumO_k(const uint32_t* __restrict__ st, uint32_t* __restrict__ S) {
    long idx = (long)blockIdx.x * 256 + threadIdx.x;
    if (idx >= (long)BB * (HIDC/2) * PHW) return;
    int b = (int)(idx / ((HIDC/2) * PHW));
    long r = idx - (long)b * (HIDC/2) * PHW;
    const uint32_t* p = st + (long)b * OO * (HIDC/2) * PHW + r;
    float lo = 0.f, hi = 0.f;
    #pragma unroll
    for (int o = 0; o < OO; o++) {
        __half2 h = *(const __half2*)&p[(long)o * (HIDC/2) * PHW];
        lo += __low2float(h); hi += __high2float(h);
    }
    S[idx] = packh2(lo, hi);
}
// enc per-object: states = half2(relu(baseA + baseB + conv3x3(mask, enc_w[:,256])))
__global__ void __launch_bounds__(256) enc_obj_k(
    const float* __restrict__ masks, const float* __restrict__ enc_w,
    const float* __restrict__ pbase, uint32_t* __restrict__ pst)
{
    __shared__ float wm[HIDC * 9];
    const int tid = threadIdx.x;
    const int img = blockIdx.y;
    const int p   = blockIdx.x * 256 + tid;
    for (int t = tid; t < HIDC * 9; t += 256) {
        int oc = t / 9, k = t - oc * 9;
        wm[t] = enc_w[((long)oc * 257 + 256) * 9 + k];
    }
    __syncthreads();
    const int y = p >> 6, x = p & 63;
    float m[3][3];
    #pragma unroll
    for (int i = 0; i < 3; i++)
        #pragma unroll
        for (int j = 0; j < 3; j++) {
            int gy = y - 1 + i, gx = x - 1 + j;
            m[i][j] = ((unsigned)gy < 64u && (unsigned)gx < 64u)
                        ? masks[(long)img * HW + gy * 64 + gx] : 0.f;
        }
    const int b = img >> 3;
    const int pp = (y + 1) * PW + x + 1;
    const float* bimg  = pbase + (long)b * HIDC * PHW;
    const float* bimg2 = bimg + (long)BB * HIDC * PHW;
    uint32_t* simg = pst + (long)img * (HIDC/2) * PHW;
    #pragma unroll 2
    for (int j = 0; j < HIDC/2; j++) {
        float a0 = bimg[(2*j) * PHW + pp]   + bimg2[(2*j) * PHW + pp];
        float a1 = bimg[(2*j+1) * PHW + pp] + bimg2[(2*j+1) * PHW + pp];
        #pragma unroll
        for (int k = 0; k < 9; k++) {
            a0 = fmaf(wm[(2*j) * 9 + k],   m[k/3][k%3], a0);
            a1 = fmaf(wm[(2*j+1) * 9 + k], m[k/3][k%3], a1);
        }
        simg[j * PHW + pp] = packh2(fmaxf(a0, 0.f), fmaxf(a1, 0.f));
    }
}

// ---------------------------------------------------------------------------
// Readout tile kernels: stage 64 ck x 4 padded rows via ONE cp.async round,
// one barrier, then fp32-accum dot over (ck, tap). 2 threads per px split ck.
// ---------------------------------------------------------------------------
__global__ void __launch_bounds__(256) ro_base_k(
    const uint32_t* __restrict__ pfeats, const uint32_t* __restrict__ wrof,
    const float* __restrict__ ro_b, float* __restrict__ rpart)
{
    extern __shared__ __align__(16) uint32_t sm[];
    uint32_t* ws  = sm + RO_TILE_U32;
    float*    red = (float*)(ws + 576);
    const int tid = threadIdx.x;
    const int img = blockIdx.y, z = blockIdx.z, row0 = blockIdx.x * 2;
    const uint32_t* pimg = pfeats + (long)img * (CC/2) * PHW + (long)z * 64 * PHW;
    const uint32_t smb = (uint32_t)__cvta_generic_to_shared(sm);
    #pragma unroll
    for (int j = 0; j < 18; j++) {
        const int o = tid + j * 256;          // 4608 lines
        const int ck = o / 72, rem = o % 72, rI = rem / 18, q = rem % 18;
        CP16(smb + (ck * B_CKSTR + rI * 72 + q * 4) * 4,
             pimg + (long)ck * PHW + (row0 + rI) * PW + q * 4);
    }
    for (int t = tid; t < 576; t += 256) ws[t] = wrof[z * 576 + t];
    asm volatile("cp.async.commit_group;" ::: "memory");
    asm volatile("cp.async.wait_group 0;" ::: "memory");
    __syncthreads();

    const int px = tid & 127, ckh = tid >> 7;
    const int r = px >> 6, x = px & 63;
    float acc = 0.f;
    for (int ck = ckh * 32; ck < ckh * 32 + 32; ck++) {
        #pragma unroll
        for (int tap = 0; tap < 9; tap++) {
            const int dy = tap / 3 - 1, dx = tap % 3 - 1;
            uint32_t bv = sm[ck * B_CKSTR + (r + 1 + dy) * 72 + (x + 1 + dx)];
            float2 bf = __half22float2(*(__half2*)&bv);
            float2 wf = __half22float2(*(__half2*)&ws[tap * 64 + ck]);
            acc = fmaf(bf.x, wf.x, acc);
            acc = fmaf(bf.y, wf.y, acc);
        }
    }
    red[tid] = acc;
    __syncthreads();
    if (tid < 128) {
        float s = red[tid] + red[tid + 128] + (z == 0 ? ro_b[0] : 0.f);
        rpart[((long)z * BB + img) * HW + (row0 + r) * 64 + x] = s;
    }
}
__global__ void __launch_bounds__(256) ro_obj_k(
    const uint32_t* __restrict__ pst, const uint32_t* __restrict__ wroh,
    const float* __restrict__ rpart, float* __restrict__ outp)
{
    extern __shared__ __align__(16) uint32_t sm[];
    uint32_t* ws  = sm + RO_TILE_U32;
    float*    red = (float*)(ws + 576);
    const int tid = threadIdx.x;
    const int img = blockIdx.y, row0 = blockIdx.x * 2;
    const uint32_t* pimg = pst + (long)img * (HIDC/2) * PHW;
    const uint32_t smb = (uint32_t)__cvta_generic_to_shared(sm);
    #pragma unroll
    for (int j = 0; j < 18; j++) {
        const int o = tid + j * 256;
        const int ck = o / 72, rem = o % 72, rI = rem / 18, q = rem % 18;
        CP16(smb + (ck * B_CKSTR + rI * 72 + q * 4) * 4,
             pimg + (long)ck * PHW + (row0 + rI) * PW + q * 4);
    }
    for (int t = tid; t < 576; t += 256) ws[t] = wroh[t];
    asm volatile("cp.async.commit_group;" ::: "memory");
    asm volatile("cp.async.wait_group 0;" ::: "memory");
    __syncthreads();

    const int px = tid & 127, ckh = tid >> 7;
    const int r = px >> 6, x = px & 63;
    float acc = 0.f;
    for (int ck = ckh * 32; ck < ckh * 32 + 32; ck++) {
        #pragma unroll
        for (int tap = 0; tap < 9; tap++) {
            const int dy = tap / 3 - 1, dx = tap % 3 - 1;
            uint32_t bv = sm[ck * B_CKSTR + (r + 1 + dy) * 72 + (x + 1 + dx)];
            float2 bf = __half22float2(*(__half2*)&bv);
            float2 wf = __half22float2(*(__half2*)&ws[tap * 64 + ck]);
            acc = fmaf(bf.x, wf.x, acc);
            acc = fmaf(bf.y, wf.y, acc);
        }
    }
    red[tid] = acc;
    __syncthreads();
    if (tid < 128) {
        const int b = img >> 3;
        const long po = (long)b * HW + (row0 + r) * 64 + x;
        float zl = red[tid] + red[tid + 128]
                 + rpart[po] + rpart[(long)BB * HW + po];
        outp[(long)img * HW + (row0 + r) * 64 + x] = 1.f / (1.f + expf(-zl));
    }
}

// ---------------------------------------------------------------------------
extern "C" void kernel_launch(void* const* d_in, const int* in_sizes, int n_in,
                              void* d_out, int out_size)
{
    const float* feats = (const float*)d_in[0];
    const float* masks = (const float*)d_in[1];
    const float* enc_w = (const float*)d_in[4];
    const float* enc_b = (const float*)d_in[5];
    const float* gcn_w = (const float*)d_in[6];
    const float* gcn_b = (const float*)d_in[7];
    const float* ro_w  = (const float*)d_in[8];
    const float* ro_b  = (const float*)d_in[9];
    float* outp = (float*)d_out;

    uint32_t *pst0, *pst1, *pS, *pfeats, *wencp, *w2p, *wdp, *wrof, *wroh;
    float *pbase, *T, *rpart;
    cudaGetSymbolAddress((void**)&pst0,   g_pst0);
    cudaGetSymbolAddress((void**)&pst1,   g_pst1);
    cudaGetSymbolAddress((void**)&pS,     g_pS);
    cudaGetSymbolAddress((void**)&pfeats, g_pfeats);
    cudaGetSymbolAddress((void**)&pbase,  g_pbase);
    cudaGetSymbolAddress((void**)&T,      g_T);
    cudaGetSymbolAddress((void**)&rpart,  g_rpart);
    cudaGetSymbolAddress((void**)&wencp,  g_wencp);
    cudaGetSymbolAddress((void**)&w2p,    g_w2p);
    cudaGetSymbolAddress((void**)&wdp,    g_wdp);
    cudaGetSymbolAddress((void**)&wrof,   g_wrof);
    cudaGetSymbolAddress((void**)&wroh,   g_wroh);

    cudaFuncSetAttribute(conv_mma<64>,
                         cudaFuncAttributeMaxDynamicSharedMemorySize, CONV_DSM);
    cudaFuncSetAttribute(conv_mma<128>,
                         cudaFuncAttributeMaxDynamicSharedMemorySize, CONV_DSM);
    cudaFuncSetAttribute(ro_base_k,
                         cudaFuncAttributeMaxDynamicSharedMemorySize, RO_DSM);
    cudaFuncSetAttribute(ro_obj_k,
                         cudaFuncAttributeMaxDynamicSharedMemorySize, RO_DSM);

    prep_enc_pack<<<(HIDC*CC*9/2 + 255)/256, 256>>>(enc_w, wencp);
    prep_gcn_pack<<<(HIDC*HIDC*9/2 + 255)/256, 256>>>(gcn_w, w2p, wdp);
    pad_feats_k<<<(int)(((long)BB*(CC/2)*PHW + 255)/256), 256>>>(feats, pfeats);

    // enc base, K-split z=2: partials -> pbase[0], pbase[zstride]
    conv_mma<128><<<dim3(32, BB, 2), 256, CONV_DSM>>>(
        pfeats, (long)(CC/2)*PHW, wencp, enc_b, nullptr, nullptr, 0,
        pbase, (long)BB*HIDC*PHW, 2, 0);
    // enc per-object -> half2 states
    enc_obj_k<<<dim3(16, BB*OO), 256>>>(masks, enc_w, pbase, pst0);
    prep_ro_pack<<<7, 256>>>(ro_w, wrof, wroh);

    uint32_t* cur = pst0; uint32_t* nxt = pst1;
    for (int s = 0; s < 2; s++) {
        sumO_k<<<(int)(((long)BB*(HIDC/2)*PHW + 255)/256), 256>>>(cur, pS);
        // T partials = conv(S, W2) + gcn_b, K-split z=2 (fp32 unpadded)
        conv_mma<64><<<dim3(32, BB, 2), 256, CONV_DSM>>>(
            pS, (long)(HIDC/2)*PHW, w2p, gcn_b, nullptr, nullptr, 0,
            T, (long)BB*HIDC*HW, 0, 0);
        // states' = relu(conv(states, Wd) + TA + TB) -> half2 padded
        conv_mma<128><<<dim3(32, BB*OO, 1), 256, CONV_DSM>>>(
            cur, (long)(HIDC/2)*PHW, wdp, nullptr,
            T, T + (long)BB*HIDC*HW, OO, nxt, 0, 1, 1);
        uint32_t* tmp = cur; cur = nxt; nxt = tmp;
    }

    ro_base_k<<<dim3(32, BB, 2), 256, RO_DSM>>>(pfeats, wrof, ro_b, rpart);
    ro_obj_k<<<dim3(32, BB*OO), 256, RO_DSM>>>(cur, wroh, rpart, outp);
}